// round 12
// baseline (speedup 1.0000x reference)
#include <cuda_runtime.h>
#include <cstdint>

#define L      2048
#define C_IN   16
#define GROUPS 4
#define NEG_INF -1000000000.0f
#define SLOT   32          // fixed padded slots per (ch,row); overflow -> g_list
#define SENT   0x7FFFFFFF

// Padded fast-path lists: SLOT entries per (ch,row), column-sorted, padded
// with sentinel col = INT_MAX. Always fully written for every row.
__device__ float2 g_slot[(size_t)C_IN * L * SLOT];
// Full-stride overflow lists (correctness fallback when support > SLOT).
__device__ float2 g_list[(size_t)C_IN * L * L];
__device__ int    g_cnt[C_IN * L];

// ---------------------------------------------------------------------------
// Kernel 1: row-wise sparsemax (causal) -> sorted compressed nonzero list,
// PLUS zero-fill of the output's upper triangle out[ch, row, j>row].
// One block (128 thr) per (channel,row); thread t owns cols [16t,16t+16).
// ---------------------------------------------------------------------------
__global__ __launch_bounds__(128) void sparsemax_kernel(const float* __restrict__ scores,
                                                        float* __restrict__ out)
{
    const int row  = blockIdx.x;
    const int ch   = blockIdx.y;
    const int tid  = threadIdx.x;
    const int lane = tid & 31;
    const int warp = tid >> 5;            // 4 warps
    const size_t base = ((size_t)ch * L + row) * (size_t)L;
    const int j0  = tid * 16;
    const int rem = row - j0;             // valid elements: x <= rem

    // ---- issue score loads first (latency starts now) ----
    float z[16];
    if (rem >= 15) {
#pragma unroll
        for (int q = 0; q < 4; q++) {
            const float4 a = *reinterpret_cast<const float4*>(scores + base + j0 + 4 * q);
            z[4*q+0]=a.x; z[4*q+1]=a.y; z[4*q+2]=a.z; z[4*q+3]=a.w;
        }
    } else {
#pragma unroll
        for (int x = 0; x < 16; x++)
            z[x] = (x <= rem) ? scores[base + j0 + x] : NEG_INF;
    }

    // ---- zero-fill out[ch, row, row+1 .. 2047] (fire-and-forget) ----
    {
        float* orow = out + base;             // out has identical layout
        const int s  = row + 1;
        const int sa = (s + 3) & ~3;          // first 16B-aligned col
        if (tid < sa - s) orow[s + tid] = 0.0f;      // <=3 scalar edge stores
        const float4 zq = make_float4(0.f, 0.f, 0.f, 0.f);
        for (int c = sa + 4 * tid; c < L; c += 4 * 128)
            *reinterpret_cast<float4*>(orow + c) = zq;
    }

    __shared__ float  smax[4];
    __shared__ int    swtot[4];
    __shared__ float2 slist[2048];        // survivors of tau0 (capacity-proof)

    // ---- row max ----
    float m = z[0];
#pragma unroll
    for (int k = 1; k < 16; k++) m = fmaxf(m, z[k]);
#pragma unroll
    for (int o = 16; o > 0; o >>= 1) m = fmaxf(m, __shfl_xor_sync(0xffffffffu, m, o));
    if (lane == 0) smax[warp] = m;
    __syncthreads();                                           // (1)
    const float tau0 = fmaxf(fmaxf(smax[0], smax[1]), fmaxf(smax[2], smax[3])) - 1.0f;

    // ---- compact survivors of tau0 into smem, column-sorted ----
    unsigned nz = 0u;
#pragma unroll
    for (int x = 0; x < 16; x++)
        if (z[x] > tau0) nz |= (1u << x);
    const int tcnt = __popc(nz);

    int v = tcnt;                          // warp inclusive scan
#pragma unroll
    for (int o = 1; o < 32; o <<= 1) {
        const int n = __shfl_up_sync(0xffffffffu, v, o);
        if (lane >= o) v += n;
    }
    const int toff = v - tcnt;
    if (lane == 31) swtot[warp] = v;
    __syncthreads();                                           // (2)
    int wbase = 0;
#pragma unroll
    for (int w = 0; w < 4; w++)
        if (w < warp) wbase += swtot[w];
    int pos = wbase + toff;
#pragma unroll
    for (int x = 0; x < 16; x++) {
        if ((nz >> x) & 1u) {
            slist[pos] = make_float2(__int_as_float(j0 + x), z[x]);
            pos++;
        }
    }
    __syncthreads();                                           // (3)
    if (warp != 0) return;                 // warps 1-3 done

    // ---- warp 0: Michelot on the small smem list (shfl-only) ----
    const int total = swtot[0] + swtot[1] + swtot[2] + swtot[3];
    float tau = tau0;
    int prev = -1;
    for (int it = 0; it < 32; it++) {
        float S = 0.0f, C = 0.0f;
        for (int n = lane; n < total; n += 32) {
            const float y = slist[n].y;
            if (y > tau) { S += y; C += 1.0f; }
        }
#pragma unroll
        for (int o = 16; o > 0; o >>= 1) {
            S += __shfl_xor_sync(0xffffffffu, S, o);
            C += __shfl_xor_sync(0xffffffffu, C, o);
        }
        const int ci = (int)C;             // >=1 always (argmax survives)
        tau = (S - 1.0f) / C;
        if (ci == prev) break;             // support stable -> converged
        prev = ci;
    }

    // ---- final order-preserving compaction: slots (+ overflow list) ----
    float2* slot = g_slot + (size_t)(ch * L + row) * SLOT;
    float2* lst  = g_list + base;
    int opos = 0;
    for (int n0 = 0; n0 < total; n0 += 32) {
        const int n = n0 + lane;
        float2 e; bool keep = false;
        if (n < total) { e = slist[n]; keep = (e.y > tau); }
        const unsigned b = __ballot_sync(0xffffffffu, keep);
        if (keep) {
            const int k = opos + __popc(b & ((1u << lane) - 1u));
            const float2 w = make_float2(e.x, e.y - tau);
            if (k < SLOT) slot[k] = w;
            lst[k] = w;                    // overflow-safe full copy (tiny)
        }
        opos += __popc(b);
    }
    // sentinel-pad remaining slots (col = INT_MAX)
    for (int n = opos + lane; n < SLOT; n += 32)
        slot[n] = make_float2(__int_as_float(SENT), 0.0f);
    if (lane == 0) g_cnt[ch * L + row] = opos;
}

// ---------------------------------------------------------------------------
// Kernel 2: grouped 3x3 conv from sentinel-padded sorted lists + bias,
// writing ONLY the causal part (upper triangle zero-filled by kernel 1).
// One block (256 thr) per (out-row i, group g). The 12 lists are staged
// into smem ONCE per block (192 x LDG.128); compute warps read LDS.64.
// ---------------------------------------------------------------------------
__global__ __launch_bounds__(256) void conv_sparse_kernel(const float* __restrict__ weight,
                                                          const float* __restrict__ bias,
                                                          float* __restrict__ out)
{
    __shared__ float  wsm[144];        // [4 oc][4 ic][3][3]
    __shared__ float  bsm[4];
    __shared__ float2 sl[12][SLOT];    // staged lists, 3 KB

    const int i    = blockIdx.x;       // output row
    const int g    = blockIdx.y;       // group
    const int tid  = threadIdx.x;
    const int warp = tid >> 5;
    const int lane = tid & 31;
    const int j0   = tid * 8;

    if (tid < 144) wsm[tid] = weight[g * 144 + tid];
    if (tid >= 224 && tid < 228) bsm[tid - 224] = bias[g * 4 + (tid - 224)];

    // ---- stage 12 lists: thread t<192 copies 2 entries via one LDG.128 ----
    if (tid < 192) {
        const int p   = tid >> 4;          // list 0..11
        const int q   = tid & 15;          // entry pair 0..15
        const int icc = p / 3;
        const int dr  = p - icc * 3;
        const int r   = i + dr - 1;
        uint4 u = make_uint4(SENT, 0u, SENT, 0u);    // sentinel pair
        if (r >= 0 && r < L)
            u = __ldg(reinterpret_cast<const uint4*>(
                    g_slot + (size_t)((g * 4 + icc) * L + r) * SLOT + 2 * q));
        *reinterpret_cast<uint4*>(&sl[p][2 * q]) = u;
    }
    __syncthreads();

    if (warp * 256 > i) return;            // whole warp above diagonal: k1 wrote it

    // ---- prefetch all 12 (col,val) pairs from smem (overlapped LDS.64) ----
    int   ecol[12];
    float eval[12];
#pragma unroll
    for (int p = 0; p < 12; p++) {
        const float2 e = sl[p][lane];
        ecol[p] = __float_as_int(e.x);
        eval[p] = e.y;
    }

    const int wlo = warp * 256 - 1;
    const int whi = warp * 256 + 256;

    float acc[4][8];
#pragma unroll
    for (int o = 0; o < 4; o++)
#pragma unroll
        for (int x = 0; x < 8; x++) acc[o][x] = 0.0f;

#pragma unroll
    for (int p = 0; p < 12; p++) {
        const int icc = p / 3;
        const int dr  = p - icc * 3;

        unsigned hits = __ballot_sync(0xffffffffu, ecol[p] >= wlo && ecol[p] <= whi);
        while (hits) {                               // warp-uniform (~1-2 iters)
            const int n = __ffs(hits) - 1;
            hits &= hits - 1;
            const int   c = __shfl_sync(0xffffffffu, ecol[p], n);
            const float v = __shfl_sync(0xffffffffu, eval[p], n);
            const int rel = c - j0 + 1;              // tap center, 0..9 valid
            if ((unsigned)rel <= 9u) {
#pragma unroll
                for (int x = 0; x < 8; x++) {
                    const int dc = rel - x;
                    if ((unsigned)dc < 3u) {
#pragma unroll
                        for (int o = 0; o < 4; o++)
                            acc[o][x] = fmaf(wsm[((o * 4 + icc) * 3 + dr) * 3 + dc], v, acc[o][x]);
                    }
                }
            }
        }

        // ---- overflow fallback (support > SLOT): lane-31 slot is real ----
        if (__shfl_sync(0xffffffffu, ecol[p], 31) != SENT) {
            const int r  = i + dr - 1;
            const int gc = g * 4 + icc;
            const int cnt = g_cnt[gc * L + r];
            const float2* lst = g_list + ((size_t)gc * L + r) * (size_t)L;
            for (int n = SLOT; n < cnt; n++) {       // warp-uniform, broadcast
                const float2 e = __ldg(&lst[n]);
                const int rel = __float_as_int(e.x) - j0 + 1;
                if ((unsigned)rel <= 9u) {
                    const float v = e.y;
#pragma unroll
                    for (int x = 0; x < 8; x++) {
                        const int dc = rel - x;
                        if ((unsigned)dc < 3u) {
#pragma unroll
                            for (int o = 0; o < 4; o++)
                                acc[o][x] = fmaf(wsm[((o * 4 + icc) * 3 + dr) * 3 + dc], v, acc[o][x]);
                        }
                    }
                }
            }
        }
    }

    // ---- bias + store (causal part only; j>i already zero from k1) ----
    if (j0 > i) return;                    // window starts beyond diagonal
    const bool full = (j0 + 7 <= i);       // fully below diagonal: no masking
#pragma unroll
    for (int o = 0; o < 4; o++) {
        const float b = bsm[o];
        float* ob = out + ((size_t)(g * 4 + o) * L + i) * (size_t)L + j0;
        if (full) {
            float4 v0, v1;
            v0.x=acc[o][0]+b; v0.y=acc[o][1]+b; v0.z=acc[o][2]+b; v0.w=acc[o][3]+b;
            v1.x=acc[o][4]+b; v1.y=acc[o][5]+b; v1.z=acc[o][6]+b; v1.w=acc[o][7]+b;
            *reinterpret_cast<float4*>(ob)     = v0;
            *reinterpret_cast<float4*>(ob + 4) = v1;
        } else {
            // diagonal-crossing window: scalar stores up to col i only
#pragma unroll
            for (int x = 0; x < 8; x++)
                if (j0 + x <= i) ob[x] = acc[o][x] + b;
        }
    }
}

// ---------------------------------------------------------------------------
extern "C" void kernel_launch(void* const* d_in, const int* in_sizes, int n_in,
                              void* d_out, int out_size)
{
    const float* scores = (const float*)d_in[0];
    const float* weight = (const float*)d_in[1];
    const float* bias   = (const float*)d_in[2];
    float* out = (float*)d_out;

    sparsemax_kernel<<<dim3(L, C_IN), 128>>>(scores, out);
    conv_sparse_kernel<<<dim3(L, GROUPS), 256>>>(weight, bias, out);
}

// round 15
// speedup vs baseline: 1.4131x; 1.4131x over previous
#include <cuda_runtime.h>
#include <cstdint>

#define L      2048
#define C_IN   16
#define GROUPS 4
#define NEG_INF -1000000000.0f
#define SLOT   32          // fixed padded slots per (ch,row); overflow -> g_list
#define SENT   0x7FFFFFFF
#define ACCW   2056        // padded acc row: idx = out_col + 4, range [3,2052]

// Padded fast-path lists: SLOT entries per (ch,row), column-sorted, padded
// with sentinel col = INT_MAX. Always fully written for every row.
__device__ float2 g_slot[(size_t)C_IN * L * SLOT];
// Full-stride overflow lists (correctness fallback when support > SLOT).
__device__ float2 g_list[(size_t)C_IN * L * L];
__device__ int    g_cnt[C_IN * L];

// ---------------------------------------------------------------------------
// Kernel 1: row-wise sparsemax (causal) -> sorted compressed nonzero list,
// PLUS zero-fill of the output's upper triangle out[ch, row, j>row].
// One block (128 thr) per (channel,row); thread t owns cols [16t,16t+16).
// ---------------------------------------------------------------------------
__global__ __launch_bounds__(128) void sparsemax_kernel(const float* __restrict__ scores,
                                                        float* __restrict__ out)
{
    const int row  = blockIdx.x;
    const int ch   = blockIdx.y;
    const int tid  = threadIdx.x;
    const int lane = tid & 31;
    const int warp = tid >> 5;            // 4 warps
    const size_t base = ((size_t)ch * L + row) * (size_t)L;
    const int j0  = tid * 16;
    const int rem = row - j0;             // valid elements: x <= rem

    // ---- issue score loads first (latency starts now) ----
    float z[16];
    if (rem >= 15) {
#pragma unroll
        for (int q = 0; q < 4; q++) {
            const float4 a = *reinterpret_cast<const float4*>(scores + base + j0 + 4 * q);
            z[4*q+0]=a.x; z[4*q+1]=a.y; z[4*q+2]=a.z; z[4*q+3]=a.w;
        }
    } else {
#pragma unroll
        for (int x = 0; x < 16; x++)
            z[x] = (x <= rem) ? scores[base + j0 + x] : NEG_INF;
    }

    // ---- zero-fill out[ch, row, row+1 .. 2047] (fire-and-forget) ----
    {
        float* orow = out + base;             // out has identical layout
        const int s  = row + 1;
        const int sa = (s + 3) & ~3;          // first 16B-aligned col
        if (tid < sa - s) orow[s + tid] = 0.0f;      // <=3 scalar edge stores
        const float4 zq = make_float4(0.f, 0.f, 0.f, 0.f);
        for (int c = sa + 4 * tid; c < L; c += 4 * 128)
            *reinterpret_cast<float4*>(orow + c) = zq;
    }

    __shared__ float  smax[4];
    __shared__ int    swtot[4];
    __shared__ float2 slist[2048];        // survivors of tau0 (capacity-proof)

    // ---- row max ----
    float m = z[0];
#pragma unroll
    for (int k = 1; k < 16; k++) m = fmaxf(m, z[k]);
#pragma unroll
    for (int o = 16; o > 0; o >>= 1) m = fmaxf(m, __shfl_xor_sync(0xffffffffu, m, o));
    if (lane == 0) smax[warp] = m;
    __syncthreads();                                           // (1)
    const float tau0 = fmaxf(fmaxf(smax[0], smax[1]), fmaxf(smax[2], smax[3])) - 1.0f;

    // ---- compact survivors of tau0 into smem, column-sorted ----
    unsigned nz = 0u;
#pragma unroll
    for (int x = 0; x < 16; x++)
        if (z[x] > tau0) nz |= (1u << x);
    const int tcnt = __popc(nz);

    int v = tcnt;                          // warp inclusive scan
#pragma unroll
    for (int o = 1; o < 32; o <<= 1) {
        const int n = __shfl_up_sync(0xffffffffu, v, o);
        if (lane >= o) v += n;
    }
    const int toff = v - tcnt;
    if (lane == 31) swtot[warp] = v;
    __syncthreads();                                           // (2)
    int wbase = 0;
#pragma unroll
    for (int w = 0; w < 4; w++)
        if (w < warp) wbase += swtot[w];
    int pos = wbase + toff;
#pragma unroll
    for (int x = 0; x < 16; x++) {
        if ((nz >> x) & 1u) {
            slist[pos] = make_float2(__int_as_float(j0 + x), z[x]);
            pos++;
        }
    }
    __syncthreads();                                           // (3)
    if (warp != 0) return;                 // warps 1-3 done

    // ---- warp 0: Michelot on the small smem list (shfl-only) ----
    const int total = swtot[0] + swtot[1] + swtot[2] + swtot[3];
    float tau = tau0;
    int prev = -1;
    for (int it = 0; it < 32; it++) {
        float S = 0.0f, C = 0.0f;
        for (int n = lane; n < total; n += 32) {
            const float y = slist[n].y;
            if (y > tau) { S += y; C += 1.0f; }
        }
#pragma unroll
        for (int o = 16; o > 0; o >>= 1) {
            S += __shfl_xor_sync(0xffffffffu, S, o);
            C += __shfl_xor_sync(0xffffffffu, C, o);
        }
        const int ci = (int)C;             // >=1 always (argmax survives)
        tau = (S - 1.0f) / C;
        if (ci == prev) break;             // support stable -> converged
        prev = ci;
    }

    // ---- final order-preserving compaction: slots (+ overflow list) ----
    float2* slot = g_slot + (size_t)(ch * L + row) * SLOT;
    float2* lst  = g_list + base;
    int opos = 0;
    for (int n0 = 0; n0 < total; n0 += 32) {
        const int n = n0 + lane;
        float2 e; bool keep = false;
        if (n < total) { e = slist[n]; keep = (e.y > tau); }
        const unsigned b = __ballot_sync(0xffffffffu, keep);
        if (keep) {
            const int k = opos + __popc(b & ((1u << lane) - 1u));
            const float2 w = make_float2(e.x, e.y - tau);
            if (k < SLOT) slot[k] = w;
            lst[k] = w;                    // overflow-safe full copy (tiny)
        }
        opos += __popc(b);
    }
    // sentinel-pad remaining slots (col = INT_MAX)
    for (int n = opos + lane; n < SLOT; n += 32)
        slot[n] = make_float2(__int_as_float(SENT), 0.0f);
    if (lane == 0) g_cnt[ch * L + row] = opos;
}

// ---------------------------------------------------------------------------
// Kernel 2: grouped 3x3 conv, SCATTER formulation.
// One block (256 thr) per (out-row i, group g). Each list entry (c,v) of
// list (ic,dr) is scattered by its owning lane into a shared accumulator
// accs[oc][c+1-dc + 4] with 12 atomicAdds (3 taps x 4 oc). Then a dense
// phase adds bias and stores the causal prefix (upper triangle from k1).
// ---------------------------------------------------------------------------
__global__ __launch_bounds__(256) void conv_sparse_kernel(const float* __restrict__ weight,
                                                          const float* __restrict__ bias,
                                                          float* __restrict__ out)
{
    __shared__ float wsm[144];          // [4 oc][4 ic][3][3]
    __shared__ float bsm[4];
    __shared__ float accs[4][ACCW];     // idx = out_col + 4; 32.9 KB

    const int i    = blockIdx.x;        // output row
    const int g    = blockIdx.y;        // group
    const int tid  = threadIdx.x;
    const int warp = tid >> 5;
    const int lane = tid & 31;

    if (tid < 144) wsm[tid] = weight[g * 144 + tid];
    if (tid >= 144 && tid < 148) bsm[tid - 144] = bias[g * 4 + (tid - 144)];

    // ---- issue list loads early: warp w owns list w (and 8+w for w<4) ----
    int   c0 = SENT, c1 = SENT;
    float v0 = 0.0f, v1 = 0.0f;
    {
        const int p   = warp;               // lists 0..7
        const int icc = p / 3, dr = p - icc * 3;
        const int r   = i + dr - 1;
        if (r >= 0 && r < L) {
            const float2 e = __ldg(&g_slot[(size_t)((g * 4 + icc) * L + r) * SLOT + lane]);
            c0 = __float_as_int(e.x); v0 = e.y;
        }
    }
    if (warp < 4) {
        const int p   = warp + 8;           // lists 8..11
        const int icc = p / 3, dr = p - icc * 3;
        const int r   = i + dr - 1;
        if (r >= 0 && r < L) {
            const float2 e = __ldg(&g_slot[(size_t)((g * 4 + icc) * L + r) * SLOT + lane]);
            c1 = __float_as_int(e.x); v1 = e.y;
        }
    }

    // ---- zero-init accs over the needed range idx in [0, i+8) ----
    const int n4 = min(ACCW >> 2, ((i + 8) >> 2) + 1);   // float4s per oc row
#pragma unroll
    for (int o = 0; o < 4; o++) {
        float4* a4 = reinterpret_cast<float4*>(&accs[o][0]);
        for (int k = tid; k < n4; k += 256)
            a4[k] = make_float4(0.f, 0.f, 0.f, 0.f);
    }
    __syncthreads();

    // ---- scatter phase ----
    // entry (c,v) of list (icc,dr): out col j = c+1-dc gets w[dc]*v
    {
        const int p = warp;
        const int icc = p / 3, dr = p - icc * 3;
        if (c0 != SENT) {
#pragma unroll
            for (int o = 0; o < 4; o++) {
                const int wb = ((o * 4 + icc) * 3 + dr) * 3;
#pragma unroll
                for (int dc = 0; dc < 3; dc++)
                    atomicAdd(&accs[o][c0 + 5 - dc], wsm[wb + dc] * v0);
            }
        }
        // overflow fallback: entry 31 real => more entries in g_list
        if (__shfl_sync(0xffffffffu, c0, 31) != SENT) {
            const int r  = i + dr - 1;
            const int gc = g * 4 + icc;
            const int cnt = g_cnt[gc * L + r];
            const float2* lst = g_list + ((size_t)gc * L + r) * (size_t)L;
            for (int n = SLOT + lane; n < cnt; n += 32) {
                const float2 e = __ldg(&lst[n]);
                const int c = __float_as_int(e.x);
#pragma unroll
                for (int o = 0; o < 4; o++) {
                    const int wb = ((o * 4 + icc) * 3 + dr) * 3;
#pragma unroll
                    for (int dc = 0; dc < 3; dc++)
                        atomicAdd(&accs[o][c + 5 - dc], wsm[wb + dc] * e.y);
                }
            }
        }
    }
    if (warp < 4) {
        const int p = warp + 8;
        const int icc = p / 3, dr = p - icc * 3;
        if (c1 != SENT) {
#pragma unroll
            for (int o = 0; o < 4; o++) {
                const int wb = ((o * 4 + icc) * 3 + dr) * 3;
#pragma unroll
                for (int dc = 0; dc < 3; dc++)
                    atomicAdd(&accs[o][c1 + 5 - dc], wsm[wb + dc] * v1);
            }
        }
        if (__shfl_sync(0xffffffffu, c1, 31) != SENT) {
            const int r  = i + dr - 1;
            const int gc = g * 4 + icc;
            const int cnt = g_cnt[gc * L + r];
            const float2* lst = g_list + ((size_t)gc * L + r) * (size_t)L;
            for (int n = SLOT + lane; n < cnt; n += 32) {
                const float2 e = __ldg(&lst[n]);
                const int c = __float_as_int(e.x);
#pragma unroll
                for (int o = 0; o < 4; o++) {
                    const int wb = ((o * 4 + icc) * 3 + dr) * 3;
#pragma unroll
                    for (int dc = 0; dc < 3; dc++)
                        atomicAdd(&accs[o][c + 5 - dc], wsm[wb + dc] * e.y);
                }
            }
        }
    }
    __syncthreads();

    // ---- dense phase: bias + store causal prefix j in [0, i] ----
    // thread t: oc = t>>6, col4 base = (t&63)*4, stride 256 cols
    const int oc = tid >> 6;
    const int cb = (tid & 63) * 4;
    const float b = bsm[oc];
    float* orow = out + ((size_t)(g * 4 + oc) * L + i) * (size_t)L;
    for (int j = cb; j <= i; j += 256) {
        const float4 a = *reinterpret_cast<const float4*>(&accs[oc][j + 4]);
        if (j + 3 <= i) {
            float4 vq;
            vq.x = a.x + b; vq.y = a.y + b; vq.z = a.z + b; vq.w = a.w + b;
            *reinterpret_cast<float4*>(orow + j) = vq;
        } else {
            const float va[4] = {a.x, a.y, a.z, a.w};
#pragma unroll
            for (int x = 0; x < 4; x++)
                if (j + x <= i) orow[j + x] = va[x] + b;
        }
    }
}

// ---------------------------------------------------------------------------
extern "C" void kernel_launch(void* const* d_in, const int* in_sizes, int n_in,
                              void* d_out, int out_size)
{
    const float* scores = (const float*)d_in[0];
    const float* weight = (const float*)d_in[1];
    const float* bias   = (const float*)d_in[2];
    float* out = (float*)d_out;

    sparsemax_kernel<<<dim3(L, C_IN), 128>>>(scores, out);
    conv_sparse_kernel<<<dim3(L, GROUPS), 256>>>(weight, bias, out);
}